// round 1
// baseline (speedup 1.0000x reference)
#include <cuda_runtime.h>

// Output depends only on idx[..., 0]:
//   alpha-composite with binary weights selects the FIRST valid fragment,
//   and bg_mask(idx0 < 0) then overrides everything when slot 0 is empty.
//   => out = (idx0 >= 0) ? shaded[idx0] : BG(1,1,1)

#define MAX_P 131072

__device__ float4 g_shaded[MAX_P];  // rgb + pad, padded for 16B gathers

__global__ void shade_kernel(const float* __restrict__ features,
                             const float* __restrict__ normals,
                             const float* __restrict__ light_dir,
                             int P) {
    int i = blockIdx.x * blockDim.x + threadIdx.x;
    if (i >= P) return;

    float lx = light_dir[0], ly = light_dir[1], lz = light_dir[2];
    float inv = rsqrtf(lx * lx + ly * ly + lz * lz);
    lx *= inv; ly *= inv; lz *= inv;

    float nx = normals[3 * i + 0];
    float ny = normals[3 * i + 1];
    float nz = normals[3 * i + 2];
    float ndl = fabsf(nx * lx + ny * ly + nz * lz);
    float s = 0.6f + 0.8f * ndl;  // AMBIENT + DIFFUSE * diffuse_term

    float r = fminf(fmaxf(features[3 * i + 0] * s, 0.0f), 1.0f);
    float g = fminf(fmaxf(features[3 * i + 1] * s, 0.0f), 1.0f);
    float b = fminf(fmaxf(features[3 * i + 2] * s, 0.0f), 1.0f);
    g_shaded[i] = make_float4(r, g, b, 0.0f);
}

// 4 pixels per thread: 4 strided idx0 loads, 4 float4 table gathers (L2),
// 3 coalesced STG.128 (12 floats = 4 pixels * rgb).
__global__ void composite_kernel(const int* __restrict__ idx,
                                 float4* __restrict__ out4,
                                 int n_pix, int K) {
    int t = blockIdx.x * blockDim.x + threadIdx.x;
    int p0 = t * 4;
    if (p0 >= n_pix) return;

    float c[12];
#pragma unroll
    for (int j = 0; j < 4; j++) {
        int p = p0 + j;
        float4 v = make_float4(0.0f, 0.0f, 0.0f, 0.0f);
        if (p < n_pix) {
            int id = __ldg(&idx[(size_t)p * (size_t)K]);
            v = (id >= 0) ? g_shaded[id] : make_float4(1.0f, 1.0f, 1.0f, 0.0f);
        }
        c[3 * j + 0] = v.x;
        c[3 * j + 1] = v.y;
        c[3 * j + 2] = v.z;
    }

    float4* o = out4 + (size_t)t * 3;
    o[0] = make_float4(c[0], c[1], c[2], c[3]);
    o[1] = make_float4(c[4], c[5], c[6], c[7]);
    o[2] = make_float4(c[8], c[9], c[10], c[11]);
}

extern "C" void kernel_launch(void* const* d_in, const int* in_sizes, int n_in,
                              void* d_out, int out_size) {
    const int*   idx       = (const int*)d_in[0];
    const float* features  = (const float*)d_in[1];
    const float* normals   = (const float*)d_in[2];
    const float* light_dir = (const float*)d_in[3];

    int n_pix = out_size / 3;                 // N*H*W
    int K     = in_sizes[0] / n_pix;          // fragments per pixel (10)
    int P     = in_sizes[1] / 3;              // number of points (100000)
    if (P > MAX_P) P = MAX_P;

    {
        int threads = 256;
        int blocks = (P + threads - 1) / threads;
        shade_kernel<<<blocks, threads>>>(features, normals, light_dir, P);
    }
    {
        int threads = 256;
        int n_thr = (n_pix + 3) / 4;
        int blocks = (n_thr + threads - 1) / threads;
        composite_kernel<<<blocks, threads>>>(idx, (float4*)d_out, n_pix, K);
    }
}